// round 7
// baseline (speedup 1.0000x reference)
#include <cuda_runtime.h>
#include <cuda_bf16.h>
#include <cstdint>

// OctreeMaxUnpool:
//   out[(i*8 + c)*C + k] = (indices[i*C + k] == c) ? data[nempty_idx[i]*C + k] : 0
//
// R7 = R6 (best: 182.75 us, DRAM 82.7%, traffic-optimal) converted to a
// persistent grid-stride launch: grid sized to fill the chip once; each warp
// strides over rows. Removes ~65 waves of block launch/retire churn and the
// ragged tail while keeping the proven access pattern:
//   - one warp per row; each STG.128 instruction writes 512 fully contiguous
//     ascending bytes; 4 stores cover the row's 2048-B span; __stcs output
//   - __ldcs on read-once indices/nempty_idx; __ldg on reused data rows

#define NUM_CHILDREN 8

__device__ __forceinline__ float4 child_select(int4 ix, float4 d, int c) {
    float4 o;
    o.x = (ix.x == c) ? d.x : 0.0f;
    o.y = (ix.y == c) ? d.y : 0.0f;
    o.z = (ix.z == c) ? d.z : 0.0f;
    o.w = (ix.w == c) ? d.w : 0.0f;
    return o;
}

// C = 64 fast path: persistent warps, one row per warp-iteration.
__global__ void __launch_bounds__(256)
octree_unpool_warprow_pers_kernel(const float4* __restrict__ data,
                                  const int4*  __restrict__ indices,
                                  const int*   __restrict__ nempty_idx,
                                  float4*      __restrict__ out,
                                  int num)
{
    constexpr int C4 = 16;                       // float4 lanes per row
    int gtid   = blockIdx.x * blockDim.x + threadIdx.x;
    int warp   = gtid >> 5;                      // global warp id
    int nwarps = (gridDim.x * blockDim.x) >> 5;  // total warps in grid
    int t      = gtid & 31;                      // lane in warp

    int l = t & 15;                              // float4 lane within row
    int h = t >> 4;                              // half-warp id (0/1)

    for (int i = warp; i < num; i += nwarps) {
        int src = __ldcs(&nempty_idx[i]);                     // read-once
        float4 d  = __ldg(&data[(long long)src * C4 + l]);    // reused: cached
        int4   ix = __ldcs(&indices[(long long)i * C4 + l]);  // read-once

        float4* rowbase = out + (long long)i * (NUM_CHILDREN * C4);
#pragma unroll
        for (int j = 0; j < 4; j++) {
            int c = h + 2 * j;                   // child slot this thread writes
            // position within row = c*16 + l = t + 32*j (ascending contiguous)
            __stcs(rowbase + t + 32 * j, child_select(ix, d, c));
        }
    }
}

// Generic-C vectorized kernel (runtime C4) for C % 4 == 0 but C != 64.
__global__ void __launch_bounds__(256)
octree_unpool_vec_dyn_kernel(const float4* __restrict__ data,
                             const int4*  __restrict__ indices,
                             const int*   __restrict__ nempty_idx,
                             float4*      __restrict__ out,
                             int num, int C4)
{
    int gtid = blockIdx.x * blockDim.x + threadIdx.x;
    int i    = gtid / C4;
    int lane = gtid - i * C4;
    if (i >= num) return;

    int src = __ldcs(&nempty_idx[i]);
    float4 d  = __ldg(&data[(long long)src * C4 + lane]);
    int4   ix = __ldcs(&indices[(long long)i * C4 + lane]);

    long long base = (long long)i * (NUM_CHILDREN * C4) + lane;
#pragma unroll
    for (int c = 0; c < NUM_CHILDREN; c++) {
        out[base + (long long)c * C4] = child_select(ix, d, c);
    }
}

// Scalar fallback for arbitrary C.
__global__ void __launch_bounds__(256)
octree_unpool_scalar_kernel(const float* __restrict__ data,
                            const int*   __restrict__ indices,
                            const int*   __restrict__ nempty_idx,
                            float*       __restrict__ out,
                            int num, int C)
{
    long long gtid = (long long)blockIdx.x * blockDim.x + threadIdx.x;
    long long total = (long long)num * C;
    if (gtid >= total) return;
    int i = (int)(gtid / C);
    int k = (int)(gtid - (long long)i * C);

    int src  = __ldcs(&nempty_idx[i]);
    float dv = __ldg(&data[(long long)src * C + k]);
    int   ix = __ldcs(&indices[(long long)i * C + k]);

    long long base = ((long long)i * NUM_CHILDREN) * C + k;
#pragma unroll
    for (int c = 0; c < NUM_CHILDREN; c++) {
        out[base + (long long)c * C] = (ix == c) ? dv : 0.0f;
    }
}

extern "C" void kernel_launch(void* const* d_in, const int* in_sizes, int n_in,
                              void* d_out, int out_size)
{
    const float* data       = (const float*)d_in[0];
    const int*   indices    = (const int*)d_in[1];
    const int*   nempty_idx = (const int*)d_in[2];
    // d_in[3] = depth (unused: the gather is already expressed by nempty_idx)

    float* out = (float*)d_out;

    int num = in_sizes[2];
    int C   = (num > 0) ? (in_sizes[1] / num) : 0;

    if (num <= 0 || C <= 0) return;

    if (C == 64) {
        // Persistent launch: ~8 CTAs of 256 threads per SM on 152 SMs.
        int block = 256;
        int grid  = 152 * 8;                     // 1216 CTAs = 9728 warps
        long long warps_needed = (long long)num; // one warp-iter per row
        long long warps_avail  = (long long)grid * (block / 32);
        if (warps_avail > warps_needed) {
            grid = (int)((warps_needed + (block / 32) - 1) / (block / 32));
            if (grid < 1) grid = 1;
        }
        octree_unpool_warprow_pers_kernel<<<grid, block>>>(
            (const float4*)data, (const int4*)indices, nempty_idx,
            (float4*)out, num);
    } else if ((C & 3) == 0) {
        int C4 = C >> 2;
        long long threads = (long long)num * C4;
        int block = 256;
        int grid  = (int)((threads + block - 1) / block);
        octree_unpool_vec_dyn_kernel<<<grid, block>>>(
            (const float4*)data, (const int4*)indices, nempty_idx,
            (float4*)out, num, C4);
    } else {
        long long threads = (long long)num * C;
        int block = 256;
        int grid  = (int)((threads + block - 1) / block);
        octree_unpool_scalar_kernel<<<grid, block>>>(
            data, indices, nempty_idx, out, num, C);
    }
}

// round 8
// speedup vs baseline: 1.1677x; 1.1677x over previous
#include <cuda_runtime.h>
#include <cuda_bf16.h>
#include <cstdint>

// OctreeMaxUnpool:
//   out[(i*8 + c)*C + k] = (indices[i*C + k] == c) ? data[nempty_idx[i]*C + k] : 0
//
// FINAL (= R6, best across 7 measured variants: 182.8 us, DRAM 82.7%,
// traffic at the compulsory minimum ~1.18 GB).
//  - One warp per row (C=64): every STG.128 instruction writes 512 fully
//    contiguous ascending bytes; 4 stores cover the row's 2048-B span.
//  - __stcs on the write-once output (full-line-per-instruction pattern).
//  - __ldcs on the read-once indices / nempty_idx streams; __ldg on the
//    gathered data rows (~32% duplication -> keep L2-cached).
//  - Flat launch (62,500 CTAs): the CTA scheduler overlaps fresh blocks'
//    front-batched loads; persistent/grid-stride variants serialize on the
//    per-row dependent chain and lose ~15% DRAM utilization (measured).

#define NUM_CHILDREN 8

__device__ __forceinline__ float4 child_select(int4 ix, float4 d, int c) {
    float4 o;
    o.x = (ix.x == c) ? d.x : 0.0f;
    o.y = (ix.y == c) ? d.y : 0.0f;
    o.z = (ix.z == c) ? d.z : 0.0f;
    o.w = (ix.w == c) ? d.w : 0.0f;
    return o;
}

// C = 64 fast path: one warp per row.
__global__ void __launch_bounds__(256)
octree_unpool_warprow_kernel(const float4* __restrict__ data,
                             const int4*  __restrict__ indices,
                             const int*   __restrict__ nempty_idx,
                             float4*      __restrict__ out,
                             int num)
{
    constexpr int C4 = 16;                       // float4 lanes per row
    int gtid = blockIdx.x * blockDim.x + threadIdx.x;
    int i    = gtid >> 5;                        // row = warp id
    int t    = gtid & 31;                        // lane in warp
    if (i >= num) return;

    int l = t & 15;                              // float4 lane within row
    int h = t >> 4;                              // half-warp id (0/1)

    int src = __ldcs(&nempty_idx[i]);            // read-once: evict-first
    float4 d  = __ldg(&data[(long long)src * C4 + l]);      // reused: cached
    int4   ix = __ldcs(&indices[(long long)i * C4 + l]);    // read-once

    float4* rowbase = out + (long long)i * (NUM_CHILDREN * C4);
#pragma unroll
    for (int j = 0; j < 4; j++) {
        int c = h + 2 * j;                       // child slot this thread writes
        // position within row = c*16 + l = t + 32*j  (ascending contiguous)
        __stcs(rowbase + t + 32 * j, child_select(ix, d, c));
    }
}

// Generic-C vectorized kernel (runtime C4) for C % 4 == 0 but C != 64.
__global__ void __launch_bounds__(256)
octree_unpool_vec_dyn_kernel(const float4* __restrict__ data,
                             const int4*  __restrict__ indices,
                             const int*   __restrict__ nempty_idx,
                             float4*      __restrict__ out,
                             int num, int C4)
{
    int gtid = blockIdx.x * blockDim.x + threadIdx.x;
    int i    = gtid / C4;
    int lane = gtid - i * C4;
    if (i >= num) return;

    int src = __ldcs(&nempty_idx[i]);
    float4 d  = __ldg(&data[(long long)src * C4 + lane]);
    int4   ix = __ldcs(&indices[(long long)i * C4 + lane]);

    long long base = (long long)i * (NUM_CHILDREN * C4) + lane;
#pragma unroll
    for (int c = 0; c < NUM_CHILDREN; c++) {
        out[base + (long long)c * C4] = child_select(ix, d, c);
    }
}

// Scalar fallback for arbitrary C.
__global__ void __launch_bounds__(256)
octree_unpool_scalar_kernel(const float* __restrict__ data,
                            const int*   __restrict__ indices,
                            const int*   __restrict__ nempty_idx,
                            float*       __restrict__ out,
                            int num, int C)
{
    long long gtid = (long long)blockIdx.x * blockDim.x + threadIdx.x;
    long long total = (long long)num * C;
    if (gtid >= total) return;
    int i = (int)(gtid / C);
    int k = (int)(gtid - (long long)i * C);

    int src  = __ldcs(&nempty_idx[i]);
    float dv = __ldg(&data[(long long)src * C + k]);
    int   ix = __ldcs(&indices[(long long)i * C + k]);

    long long base = ((long long)i * NUM_CHILDREN) * C + k;
#pragma unroll
    for (int c = 0; c < NUM_CHILDREN; c++) {
        out[base + (long long)c * C] = (ix == c) ? dv : 0.0f;
    }
}

extern "C" void kernel_launch(void* const* d_in, const int* in_sizes, int n_in,
                              void* d_out, int out_size)
{
    const float* data       = (const float*)d_in[0];
    const int*   indices    = (const int*)d_in[1];
    const int*   nempty_idx = (const int*)d_in[2];
    // d_in[3] = depth (unused: the gather is already expressed by nempty_idx)

    float* out = (float*)d_out;

    int num = in_sizes[2];
    int C   = (num > 0) ? (in_sizes[1] / num) : 0;

    if (num <= 0 || C <= 0) return;

    if (C == 64) {
        long long threads = (long long)num * 32;   // one warp per row
        int block = 256;
        int grid  = (int)((threads + block - 1) / block);
        octree_unpool_warprow_kernel<<<grid, block>>>(
            (const float4*)data, (const int4*)indices, nempty_idx,
            (float4*)out, num);
    } else if ((C & 3) == 0) {
        int C4 = C >> 2;
        long long threads = (long long)num * C4;
        int block = 256;
        int grid  = (int)((threads + block - 1) / block);
        octree_unpool_vec_dyn_kernel<<<grid, block>>>(
            (const float4*)data, (const int4*)indices, nempty_idx,
            (float4*)out, num, C4);
    } else {
        long long threads = (long long)num * C;
        int block = 256;
        int grid  = (int)((threads + block - 1) / block);
        octree_unpool_scalar_kernel<<<grid, block>>>(
            data, indices, nempty_idx, out, num, C);
    }
}